// round 14
// baseline (speedup 1.0000x reference)
#include <cuda_runtime.h>
#include <cuda_bf16.h>
#include <math.h>
#include <stdint.h>

#define B_ 8
#define C_ 512
#define T_ 8192
#define P_ 512
#define K_ 30
#define M_ (B_ * P_)          // 4096 rows through the MLP

// output layout (concatenated tuple, fp32)
#define VIDEO_OFF 0
#define JOINT_OFF (VIDEO_OFF + B_ * K_)                 // 240
#define CLS_OFF   (JOINT_OFF + M_ * K_)                 // 123120
#define DET_OFF   (CLS_OFF + M_ * K_)                   // 246000
#define H7_OFF    (DET_OFF + M_ * K_)                   // 368880

// ------------------------- scratch (no cudaMalloc) -------------------------
__device__ float          g_pooled[B_ * C_ * P_];        // [B*C, P]
__device__ __nv_bfloat16  g_fH[M_ * C_],   g_fL[M_ * C_];
__device__ __nv_bfloat16  g_W6H[1024 * 512], g_W6L[1024 * 512];
__device__ __nv_bfloat16  g_W7H[512 * 1024], g_W7L[512 * 1024];
__device__ __nv_bfloat16  g_h6H[M_ * 1024],  g_h6L[M_ * 1024];
__device__ __nv_bfloat16  g_h7H[M_ * 512],   g_h7L[M_ * 512];
__device__ __nv_bfloat16  g_WhdH[128 * 512], g_WhdL[128 * 512];
__device__ float          g_bhd[128];
__device__ float          g_cprob[M_ * K_];

// ------------------------- helpers -------------------------
__device__ __forceinline__ uint32_t smem_u32(const void* p) {
    uint32_t a;
    asm("{ .reg .u64 t; cvta.to.shared.u64 t, %1; cvt.u32.u64 %0, t; }" : "=r"(a) : "l"(p));
    return a;
}
__device__ __forceinline__ void ldsm4(uint32_t addr, uint32_t r[4]) {
    asm volatile("ldmatrix.sync.aligned.m8n8.x4.shared.b16 {%0,%1,%2,%3}, [%4];"
        : "=r"(r[0]), "=r"(r[1]), "=r"(r[2]), "=r"(r[3]) : "r"(addr));
}
__device__ __forceinline__ void mma16816(float c[4], const uint32_t a[4],
                                         uint32_t b0, uint32_t b1) {
    asm volatile("mma.sync.aligned.m16n8k16.row.col.f32.bf16.bf16.f32 "
        "{%0,%1,%2,%3}, {%4,%5,%6,%7}, {%8,%9}, {%0,%1,%2,%3};"
        : "+f"(c[0]), "+f"(c[1]), "+f"(c[2]), "+f"(c[3])
        : "r"(a[0]), "r"(a[1]), "r"(a[2]), "r"(a[3]), "r"(b0), "r"(b1));
}
#define CPASYNC(dst, src) \
    asm volatile("cp.async.cg.shared.global [%0], [%1], 16;" :: "r"(dst), "l"(src))
#define CP_COMMIT() asm volatile("cp.async.commit_group;" ::: "memory")
#define CP_WAIT(n)  asm volatile("cp.async.wait_group %0;" :: "n"(n) : "memory")

__device__ __forceinline__ float warp_sum(float v) {
#pragma unroll
    for (int o = 16; o > 0; o >>= 1) v += __shfl_xor_sync(0xffffffffu, v, o);
    return v;
}
__device__ __forceinline__ float warp_max(float v) {
#pragma unroll
    for (int o = 16; o > 0; o >>= 1) v = fmaxf(v, __shfl_xor_sync(0xffffffffu, v, o));
    return v;
}

// ---------------------------------------------------------------------------
// Kernel 1: per-(b,c) row scan in smem (shuffle-based) + answer proposals
// ---------------------------------------------------------------------------
__global__ void pool_kernel(const float* __restrict__ x,
                            const void* __restrict__ boxes_raw,
                            float* __restrict__ pooled) {
    const int bc = blockIdx.x;
    const int b = bc / C_;
    const float* row = x + (size_t)bc * T_;

    __shared__ float cs[256 * 33];
    __shared__ float wsum[8];
    const int t = threadIdx.x;
    const int warp = t >> 5, lane = t & 31;

    for (int j4 = t; j4 < T_ / 4; j4 += 256) {
        float4 v = reinterpret_cast<const float4*>(row)[j4];
        int j = j4 * 4;
        int base = (j >> 5) * 33 + (j & 31);
        cs[base + 0] = v.x; cs[base + 1] = v.y; cs[base + 2] = v.z; cs[base + 3] = v.w;
    }
    __syncthreads();

    float run = 0.f;
    const int base = t * 33;
#pragma unroll
    for (int i = 0; i < 32; i++) { run += cs[base + i]; cs[base + i] = run; }

    float incl = run;
#pragma unroll
    for (int o = 1; o < 32; o <<= 1) {
        float up = __shfl_up_sync(0xffffffffu, incl, o);
        if (lane >= o) incl += up;
    }
    if (lane == 31) wsum[warp] = incl;
    __syncthreads();

    float wofs = 0.f;
#pragma unroll
    for (int wv = 0; wv < 8; wv++) wofs += (wv < warp) ? wsum[wv] : 0.f;
    const float ofs = wofs + (incl - run);
#pragma unroll
    for (int i = 0; i < 32; i++) cs[base + i] += ofs;
    __syncthreads();

    const long long* b64all = (const long long*)boxes_raw;
    long long s0 = b64all[0], e0 = b64all[1];
    bool is64 = (s0 >= 0 && s0 < T_ && e0 >= 1 && e0 <= T_ && e0 > s0);

    for (int p = t; p < P_; p += 256) {
        int s, e;
        if (is64) {
            const long long* bb = b64all + (size_t)b * P_ * 2;
            s = (int)bb[2 * p]; e = (int)bb[2 * p + 1];
        } else {
            const int* bb = ((const int*)boxes_raw) + (size_t)b * P_ * 2;
            s = bb[2 * p]; e = bb[2 * p + 1];
        }
        int ei = e - 1;
        float ge = cs[(ei >> 5) * 33 + (ei & 31)];
        float gs = 0.f;
        if (s > 0) { int si = s - 1; gs = cs[(si >> 5) * 33 + (si & 31)]; }
        pooled[(size_t)bc * P_ + p] = (ge - gs) / (float)(e - s);
    }
}

// ---------------------------------------------------------------------------
// Kernel 2: transpose+split (blocks 0..2047) fused with weight prep
// (blocks 2048..2639). Both independent; co-scheduled in one launch.
// ---------------------------------------------------------------------------
#define N_W6 (1024 * 512)
#define N_W7 (512 * 1024)
#define N_WHD (128 * 512)
#define TRN_BLOCKS 2048          // (C/32)*(P/32)*B = 16*16*8
#define PREP_BLOCKS 592

__global__ void transprep_kernel(const float* __restrict__ pooled,
                                 __nv_bfloat16* __restrict__ fH,
                                 __nv_bfloat16* __restrict__ fL,
                                 const float* __restrict__ W6,
                                 const float* __restrict__ W7,
                                 const float* __restrict__ Wc, const float* __restrict__ bc,
                                 const float* __restrict__ Wd, const float* __restrict__ bd,
                                 __nv_bfloat16* __restrict__ W6H, __nv_bfloat16* __restrict__ W6L,
                                 __nv_bfloat16* __restrict__ W7H, __nv_bfloat16* __restrict__ W7L,
                                 __nv_bfloat16* __restrict__ WhdH, __nv_bfloat16* __restrict__ WhdL,
                                 float* __restrict__ bhd) {
    if (blockIdx.x >= TRN_BLOCKS) {
        const int NT = N_W6 + N_W7 + N_WHD;
        const int base = (blockIdx.x - TRN_BLOCKS) * 256 + threadIdx.x;
        const int stride = PREP_BLOCKS * 256;
        for (int i = base; i < NT; i += stride) {
            float v;
            __nv_bfloat16* oh;
            __nv_bfloat16* ol;
            int li;
            if (i < N_W6) { li = i; v = W6[li]; oh = W6H; ol = W6L; }
            else if (i < N_W6 + N_W7) { li = i - N_W6; v = W7[li]; oh = W7H; ol = W7L; }
            else {
                li = i - N_W6 - N_W7;
                int r = li >> 9, k = li & 511;
                v = (r < 30) ? Wc[r * 512 + k] : ((r < 60) ? Wd[(r - 30) * 512 + k] : 0.f);
                oh = WhdH; ol = WhdL;
                if (li < 128) bhd[li] = (li < 30) ? bc[li] : ((li < 60) ? bd[li - 30] : 0.f);
            }
            __nv_bfloat16 h = __float2bfloat16_rn(v);
            oh[li] = h;
            ol[li] = __float2bfloat16_rn(v - __bfloat162float(h));
        }
        return;
    }

    // ---- transpose branch: [B,C,P] -> [B*P, C] with bf16 hi/lo split
    __shared__ float t[32][33];
    const int gb = blockIdx.x;
    const int cblk = gb & 15, pblk = (gb >> 4) & 15, b = gb >> 8;
    const int c0 = cblk * 32, p0 = pblk * 32;
    const int tx = threadIdx.x & 31, ty = threadIdx.x >> 5;
#pragma unroll
    for (int i = 0; i < 32; i += 8)
        t[ty + i][tx] = pooled[((size_t)(b * C_ + c0 + ty + i)) * P_ + p0 + tx];
    __syncthreads();
#pragma unroll
    for (int i = 0; i < 32; i += 8) {
        size_t row = (size_t)(b * P_ + p0 + ty + i);
        float v = t[tx][ty + i];
        __nv_bfloat16 h = __float2bfloat16_rn(v);
        fH[row * C_ + c0 + tx] = h;
        fL[row * C_ + c0 + tx] = __float2bfloat16_rn(v - __bfloat162float(h));
    }
}

// ---------------------------------------------------------------------------
// mma.sync bf16-split GEMM: C[BM x 128 tile] = act(A[M,K] @ W[N,K]^T + bias)
// 256 threads = 8 warps (2m x 4n), warp tile (BM/2)x32, atoms m16n8k16.
// 3-term split: AH*BH + AH*BL + AL*BH.  cp.async 3-stage, ldmatrix frags.
// MINB: min blocks/SM via launch_bounds (3 for BM=64 to lift occupancy).
// MODE 0: relu -> bf16 hi/lo.  MODE 1: relu -> f32 + bf16 hi/lo.
// MODE 2: heads (BM=64): in-register class softmax (quad shfl).
// ---------------------------------------------------------------------------
#define N_STAGES 3

template <int BM, int MODE, int MINB>
__global__ __launch_bounds__(256, MINB) void gemm_mma(
    const __nv_bfloat16* __restrict__ AH, const __nv_bfloat16* __restrict__ AL,
    const __nv_bfloat16* __restrict__ BH, const __nv_bfloat16* __restrict__ BL,
    const float* __restrict__ bias, int K, int ldC,
    float* __restrict__ outF, __nv_bfloat16* __restrict__ outH,
    __nv_bfloat16* __restrict__ outL,
    float* __restrict__ detO, float* __restrict__ cprob) {

    constexpr int MAC  = BM / 32;            // m-atoms per warp
    constexpr int AGPS = BM * 4;             // A 16B-groups per split per stage
    constexpr int AUN  = (2 * AGPS) / 256;   // A cp.async per thread
    constexpr int ASB  = BM * 64;            // A split bytes
    constexpr int BBASE = 2 * ASB;           // B region offset in stage
    constexpr int STGB = BBASE + 16384;      // stage bytes

    extern __shared__ char smem[];
    const uint32_t sbase = smem_u32(smem);

    const int tid = threadIdx.x;
    const int lane = tid & 31, wid = tid >> 5;
    const int wm = wid >> 2, wn = wid & 3;
    const int m0 = blockIdx.y * BM, n0 = blockIdx.x * 128;

    // ---- global->smem staging indices
    uint32_t offA[AUN], offB[4];
    const __nv_bfloat16* srcA[AUN];
    const __nv_bfloat16* srcB[4];
#pragma unroll
    for (int u = 0; u < AUN; u++) {
        int id = tid + u * 256;
        int split = id / AGPS, g = id % AGPS, row = g >> 2, seg = g & 3;
        uint32_t sw = (uint32_t)(((((row & 1) << 2) + seg) ^ ((row >> 1) & 7)) << 4);
        offA[u] = (uint32_t)(split * ASB + (row >> 1) * 128) + sw;
        srcA[u] = (split ? AL : AH) + (size_t)(m0 + row) * K + seg * 8;
    }
#pragma unroll
    for (int u = 0; u < 4; u++) {
        int id = tid + u * 256;
        int split = id >> 9, g = id & 511, row = g >> 2, seg = g & 3;
        uint32_t sw = (uint32_t)(((((row & 1) << 2) + seg) ^ ((row >> 1) & 7)) << 4);
        offB[u] = (uint32_t)(BBASE + split * 8192 + (row >> 1) * 128) + sw;
        srcB[u] = (split ? BL : BH) + (size_t)(n0 + row) * K + seg * 8;
    }

    // ---- ldmatrix per-lane address components
    const int laneRow = (lane & 7) | (((lane >> 3) & 1) << 3);
    const int segAdd = (lane >> 4) & 1;
    uint32_t pA1[MAC]; int pA2[MAC], pA3[MAC];
#pragma unroll
    for (int ma = 0; ma < MAC; ma++) {
        int row = wm * (BM / 2) + ma * 16 + laneRow;
        pA1[ma] = (uint32_t)((row >> 1) * 128);
        pA2[ma] = (row & 1) << 2;
        pA3[ma] = (row >> 1) & 7;
    }
    uint32_t pB1[2]; int pB2[2], pB3[2];
#pragma unroll
    for (int nb = 0; nb < 2; nb++) {
        int row = wn * 32 + nb * 16 + laneRow;
        pB1[nb] = (uint32_t)((row >> 1) * 128);
        pB2[nb] = (row & 1) << 2;
        pB3[nb] = (row >> 1) & 7;
    }

    float acc[MAC][4][4];
#pragma unroll
    for (int i = 0; i < MAC; i++)
#pragma unroll
        for (int j = 0; j < 4; j++)
#pragma unroll
            for (int q = 0; q < 4; q++) acc[i][j][q] = 0.f;

    const int NIT = K >> 5;

    // prologue: stages 0 and 1
#pragma unroll
    for (int u = 0; u < AUN; u++) CPASYNC(sbase + offA[u], srcA[u]);
#pragma unroll
    for (int u = 0; u < 4; u++) CPASYNC(sbase + offB[u], srcB[u]);
    CP_COMMIT();
    if (NIT > 1) {
        const uint32_t sb = sbase + STGB;
#pragma unroll
        for (int u = 0; u < AUN; u++) CPASYNC(sb + offA[u], srcA[u] + 32);
#pragma unroll
        for (int u = 0; u < 4; u++) CPASYNC(sb + offB[u], srcB[u] + 32);
        CP_COMMIT();
    }

    int st = 0, ld = 2;
    for (int it = 0; it < NIT; it++) {
        if (it + 1 < NIT) { CP_WAIT(1); } else { CP_WAIT(0); }
        __syncthreads();

        if (it + 2 < NIT) {
            const int kpos = (it + 2) << 5;
            const uint32_t sb = sbase + ld * STGB;
#pragma unroll
            for (int u = 0; u < AUN; u++) CPASYNC(sb + offA[u], srcA[u] + kpos);
#pragma unroll
            for (int u = 0; u < 4; u++) CPASYNC(sb + offB[u], srcB[u] + kpos);
            CP_COMMIT();
        }

        const uint32_t stb = sbase + st * STGB;
#pragma unroll
        for (int ks = 0; ks < 2; ks++) {
            uint32_t aH[MAC][4], aL[MAC][4];
#pragma unroll
            for (int ma = 0; ma < MAC; ma++) {
                uint32_t swz = (uint32_t)(((pA2[ma] + ks * 2 + segAdd) ^ pA3[ma]) << 4);
                ldsm4(stb + pA1[ma] + swz, aH[ma]);
                ldsm4(stb + ASB + pA1[ma] + swz, aL[ma]);
            }
            uint32_t bH[2][4], bL[2][4];
#pragma unroll
            for (int nb = 0; nb < 2; nb++) {
                uint32_t swz = (uint32_t)(((pB2[nb] + ks * 2 + segAdd) ^ pB3[nb]) << 4);
                ldsm4(stb + BBASE + pB1[nb] + swz, bH[nb]);
                ldsm4(stb + BBASE + 8192 + pB1[nb] + swz, bL[nb]);
            }
#pragma unroll
            for (int ma = 0; ma < MAC; ma++)
#pragma unroll
                for (int na = 0; na < 4; na++) {
                    uint32_t b0h = bH[na >> 1][na & 1], b1h = bH[na >> 1][2 + (na & 1)];
                    uint32_t b0l = bL[na >> 1][na & 1], b1l = bL[na >> 1][2 + (na & 1)];
                    mma16816(acc[ma][na], aH[ma], b0h, b1h);
                    mma16816(acc[ma][na], aH[ma], b0l, b1l);
                    mma16816(acc[ma][na], aL[ma], b0h, b1h);
                }
        }
        st = (st + 1 == N_STAGES) ? 0 : st + 1;
        ld = (ld + 1 == N_STAGES) ? 0 : ld + 1;
    }

    // ---- epilogue
    const int tr = lane >> 2, tc = (lane & 3) * 2;

    if (MODE == 2) {
        // heads: wn=0 holds cols 0..31 (class 0..29 + det 0,1);
        //        wn=1 holds cols 32..63 (det 2..29 + pad). wn>=2: all pad.
        if (wn <= 1) {
#pragma unroll
            for (int ma = 0; ma < MAC; ma++) {
                const int r0 = m0 + wm * (BM / 2) + ma * 16 + tr;
                const int r1 = r0 + 8;
                float v0[8], v1[8];
#pragma unroll
                for (int na = 0; na < 4; na++) {
                    const int col = wn * 32 + na * 8 + tc;
                    const float b0 = bias[col], b1 = bias[col + 1];
                    v0[na * 2 + 0] = acc[ma][na][0] + b0;
                    v0[na * 2 + 1] = acc[ma][na][1] + b1;
                    v1[na * 2 + 0] = acc[ma][na][2] + b0;
                    v1[na * 2 + 1] = acc[ma][na][3] + b1;
                }
                if (wn == 0) {
                    float mx0 = -INFINITY, mx1 = -INFINITY;
#pragma unroll
                    for (int j = 0; j < 8; j++) {
                        const int col = (j >> 1) * 8 + tc + (j & 1);
                        if (col < 30) { mx0 = fmaxf(mx0, v0[j]); mx1 = fmaxf(mx1, v1[j]); }
                    }
                    mx0 = fmaxf(mx0, __shfl_xor_sync(0xffffffffu, mx0, 1));
                    mx0 = fmaxf(mx0, __shfl_xor_sync(0xffffffffu, mx0, 2));
                    mx1 = fmaxf(mx1, __shfl_xor_sync(0xffffffffu, mx1, 1));
                    mx1 = fmaxf(mx1, __shfl_xor_sync(0xffffffffu, mx1, 2));
                    float e0[8], e1[8], s0 = 0.f, s1 = 0.f;
#pragma unroll
                    for (int j = 0; j < 8; j++) {
                        const int col = (j >> 1) * 8 + tc + (j & 1);
                        if (col < 30) {
                            e0[j] = expf(v0[j] - mx0); s0 += e0[j];
                            e1[j] = expf(v1[j] - mx1); s1 += e1[j];
                        } else { e0[j] = 0.f; e1[j] = 0.f; }
                    }
                    s0 += __shfl_xor_sync(0xffffffffu, s0, 1);
                    s0 += __shfl_xor_sync(0xffffffffu, s0, 2);
                    s1 += __shfl_xor_sync(0xffffffffu, s1, 1);
                    s1 += __shfl_xor_sync(0xffffffffu, s1, 2);
                    const float i0 = 1.f / s0, i1 = 1.f / s1;
#pragma unroll
                    for (int na = 0; na < 4; na++) {
                        const int col = na * 8 + tc;
                        if (col < 30) {
                            *(float2*)(outF + (size_t)r0 * K_ + col) =
                                make_float2(v0[na * 2], v0[na * 2 + 1]);
                            *(float2*)(outF + (size_t)r1 * K_ + col) =
                                make_float2(v1[na * 2], v1[na * 2 + 1]);
                            *(float2*)(cprob + (size_t)r0 * K_ + col) =
                                make_float2(e0[na * 2] * i0, e0[na * 2 + 1] * i0);
                            *(float2*)(cprob + (size_t)r1 * K_ + col) =
                                make_float2(e1[na * 2] * i1, e1[na * 2 + 1] * i1);
                        } else {          // col == 30: det logits 0,1
                            *(float2*)(detO + (size_t)r0 * K_ + 0) =
                                make_float2(v0[na * 2], v0[na * 2 + 1]);
                            *(float2*)(detO + (size_t)r1 * K_ + 0) =
                                make_float2(v1[na * 2], v1[na * 2 + 1]);
                        }
                    }
                } else {  // wn == 1: det logits 2..29 at cols 32..59
#pragma unroll
                    for (int na = 0; na < 4; na++) {
                        const int col = 32 + na * 8 + tc;
                        if (col < 60) {
                            *(float2*)(detO + (size_t)r0 * K_ + (col - 30)) =
                                make_float2(v0[na * 2], v0[na * 2 + 1]);
                            *(float2*)(detO + (size_t)r1 * K_ + (col - 30)) =
                                make_float2(v1[na * 2], v1[na * 2 + 1]);
                        }
                    }
                }
            }
        }
        return;
    }

#pragma unroll
    for (int ma = 0; ma < MAC; ma++) {
        const int r0 = m0 + wm * (BM / 2) + ma * 16 + tr;
#pragma unroll
        for (int na = 0; na < 4; na++) {
            const int col = n0 + wn * 32 + na * 8 + tc;
            const float b0 = bias[col], b1 = bias[col + 1];
            float v00 = fmaxf(acc[ma][na][0] + b0, 0.f), v01 = fmaxf(acc[ma][na][1] + b1, 0.f);
            float v10 = fmaxf(acc[ma][na][2] + b0, 0.f), v11 = fmaxf(acc[ma][na][3] + b1, 0.f);
            if (MODE == 1) {
                *(float2*)(outF + (size_t)r0 * ldC + col) = make_float2(v00, v01);
                *(float2*)(outF + (size_t)(r0 + 8) * ldC + col) = make_float2(v10, v11);
            }
            __nv_bfloat162 h0, h1, l0, l1;
            h0.x = __float2bfloat16_rn(v00); h0.y = __float2bfloat16_rn(v01);
            h1.x = __float2bfloat16_rn(v10); h1.y = __float2bfloat16_rn(v11);
            l0.x = __float2bfloat16_rn(v00 - __bfloat162float(h0.x));
            l0.y = __float2bfloat16_rn(v01 - __bfloat162float(h0.y));
            l1.x = __float2bfloat16_rn(v10 - __bfloat162float(h1.x));
            l1.y = __float2bfloat16_rn(v11 - __bfloat162float(h1.y));
            *(__nv_bfloat162*)(outH + (size_t)r0 * ldC + col) = h0;
            *(__nv_bfloat162*)(outH + (size_t)(r0 + 8) * ldC + col) = h1;
            *(__nv_bfloat162*)(outL + (size_t)r0 * ldC + col) = l0;
            *(__nv_bfloat162*)(outL + (size_t)(r0 + 8) * ldC + col) = l1;
        }
    }
}

// ---------------------------------------------------------------------------
// fused det-softmax + joint + video: one block per (b,k)
// ---------------------------------------------------------------------------
__global__ __launch_bounds__(256) void detjoint_kernel(
    const float* __restrict__ detL, const float* __restrict__ cprob,
    float* __restrict__ joint, float* __restrict__ video) {
    const int bk = blockIdx.x;
    const int b = bk / K_, k = bk % K_;
    const int tid = threadIdx.x;
    const int warp = tid >> 5, lane = tid & 31;
    __shared__ float red[8];

    const size_t i0 = ((size_t)(b * P_ + tid)) * K_ + k;
    const size_t i1 = ((size_t)(b * P_ + tid + 256)) * K_ + k;
    const float v0 = detL[i0], v1 = detL[i1];

    float mx = warp_max(fmaxf(v0, v1));
    if (lane == 0) red[warp] = mx;
    __syncthreads();
    float bm = red[0];
#pragma unroll
    for (int i = 1; i < 8; i++) bm = fmaxf(bm, red[i]);

    const float e0 = expf(v0 - bm), e1 = expf(v1 - bm);
    float sm = warp_sum(e0 + e1);
    __syncthreads();
    if (lane == 0) red[warp] = sm;
    __syncthreads();
    float bs = 0.f;
#pragma unroll
    for (int i = 0; i < 8; i++) bs += red[i];
    const float inv = 1.f / bs;

    const float j0 = cprob[i0] * e0 * inv;
    const float j1 = cprob[i1] * e1 * inv;
    joint[i0] = j0;
    joint[i1] = j1;
    float js = warp_sum(j0 + j1);
    __syncthreads();
    if (lane == 0) red[warp] = js;
    __syncthreads();
    if (tid == 0) {
        float tot = 0.f;
#pragma unroll
        for (int i = 0; i < 8; i++) tot += red[i];
        video[bk] = tot;
    }
}

// ---------------------------------------------------------------------------
extern "C" void kernel_launch(void* const* d_in, const int* in_sizes, int n_in,
                              void* d_out, int out_size) {
    const float* x  = (const float*)d_in[0];
    const void*  bx = d_in[1];
    const float* W6 = (const float*)d_in[2];
    const float* b6 = (const float*)d_in[3];
    const float* W7 = (const float*)d_in[4];
    const float* b7 = (const float*)d_in[5];
    const float* Wc = (const float*)d_in[6];
    const float* bc = (const float*)d_in[7];
    const float* Wd = (const float*)d_in[8];
    const float* bd = (const float*)d_in[9];
    float* out = (float*)d_out;

    float *pooled, *bhd, *cprob;
    __nv_bfloat16 *fH, *fL, *W6H, *W6L, *W7H, *W7L, *h6H, *h6L, *h7H, *h7L, *WhdH, *WhdL;
    cudaGetSymbolAddress((void**)&pooled, g_pooled);
    cudaGetSymbolAddress((void**)&fH, g_fH);   cudaGetSymbolAddress((void**)&fL, g_fL);
    cudaGetSymbolAddress((void**)&W6H, g_W6H); cudaGetSymbolAddress((void**)&W6L, g_W6L);
    cudaGetSymbolAddress((void**)&W7H, g_W7H); cudaGetSymbolAddress((void**)&W7L, g_W7L);
    cudaGetSymbolAddress((void**)&h6H, g_h6H); cudaGetSymbolAddress((void**)&h6L, g_h6L);
    cudaGetSymbolAddress((void**)&h7H, g_h7H); cudaGetSymbolAddress((void**)&h7L, g_h7L);
    cudaGetSymbolAddress((void**)&WhdH, g_WhdH); cudaGetSymbolAddress((void**)&WhdL, g_WhdL);
    cudaGetSymbolAddress((void**)&bhd, g_bhd);
    cudaGetSymbolAddress((void**)&cprob, g_cprob);

    float* h7    = out + H7_OFF;
    float* clsO  = out + CLS_OFF;
    float* detO  = out + DET_OFF;
    float* joint = out + JOINT_OFF;
    float* video = out + VIDEO_OFF;

    const int SMEM128 = N_STAGES * (128 * 128 + 16384);   // 98304
    const int SMEM64  = N_STAGES * (64 * 128 + 16384);    // 73728
    cudaFuncSetAttribute((gemm_mma<128, 0, 1>), cudaFuncAttributeMaxDynamicSharedMemorySize, SMEM128);
    cudaFuncSetAttribute((gemm_mma<64, 1, 3>),  cudaFuncAttributeMaxDynamicSharedMemorySize, SMEM64);
    cudaFuncSetAttribute((gemm_mma<64, 2, 3>),  cudaFuncAttributeMaxDynamicSharedMemorySize, SMEM64);

    // 1. pooled [B*C, P]
    pool_kernel<<<B_ * C_, 256>>>(x, bx, pooled);
    // 2. transpose+split fused with weight prep (independent work, one launch)
    transprep_kernel<<<TRN_BLOCKS + PREP_BLOCKS, 256>>>(
        pooled, fH, fL, W6, W7, Wc, bc, Wd, bd,
        W6H, W6L, W7H, W7L, WhdH, WhdL, bhd);

    // 3. h6 = relu(feats @ W6^T + b6) : M=4096, N=1024, K=512  (BM=128, 256 CTAs)
    gemm_mma<128, 0, 1><<<dim3(8, 32), 256, SMEM128>>>(fH, fL, W6H, W6L, b6, 512, 1024,
                                                       nullptr, h6H, h6L, nullptr, nullptr);
    // 4. h7 = relu(h6 @ W7^T + b7) : M=4096, N=512, K=1024  (BM=64, 256 CTAs, 3 CTA/SM)
    gemm_mma<64, 1, 3><<<dim3(4, 64), 256, SMEM64>>>(h6H, h6L, W7H, W7L, b7, 1024, 512,
                                                     h7, h7H, h7L, nullptr, nullptr);
    // 5. heads + fused class softmax (BM=64, 64 CTAs, 3 CTA/SM)
    gemm_mma<64, 2, 3><<<dim3(1, 64), 256, SMEM64>>>(h7H, h7L, WhdH, WhdL, bhd, 512, 0,
                                                     clsO, nullptr, nullptr, detO, cprob);

    // 6. fused det softmax + joint + video
    detjoint_kernel<<<B_ * K_, 256>>>(detO, cprob, joint, video);
}

// round 15
// speedup vs baseline: 1.0471x; 1.0471x over previous
#include <cuda_runtime.h>
#include <cuda_bf16.h>
#include <math.h>
#include <stdint.h>

#define B_ 8
#define C_ 512
#define T_ 8192
#define P_ 512
#define K_ 30
#define M_ (B_ * P_)          // 4096 rows through the MLP

// output layout (concatenated tuple, fp32)
#define VIDEO_OFF 0
#define JOINT_OFF (VIDEO_OFF + B_ * K_)                 // 240
#define CLS_OFF   (JOINT_OFF + M_ * K_)                 // 123120
#define DET_OFF   (CLS_OFF + M_ * K_)                   // 246000
#define H7_OFF    (DET_OFF + M_ * K_)                   // 368880

// ------------------------- scratch (no cudaMalloc) -------------------------
__device__ float          g_pooled[B_ * C_ * P_];        // [B*C, P]
__device__ __nv_bfloat16  g_fH[M_ * C_],   g_fL[M_ * C_];
__device__ __nv_bfloat16  g_W6H[1024 * 512], g_W6L[1024 * 512];
__device__ __nv_bfloat16  g_W7H[512 * 1024], g_W7L[512 * 1024];
__device__ __nv_bfloat16  g_h6H[M_ * 1024],  g_h6L[M_ * 1024];
__device__ __nv_bfloat16  g_h7H[M_ * 512],   g_h7L[M_ * 512];
__device__ __nv_bfloat16  g_WhdH[128 * 512], g_WhdL[128 * 512];
__device__ float          g_bhd[128];
__device__ float          g_cprob[M_ * K_];

// ------------------------- helpers -------------------------
__device__ __forceinline__ uint32_t smem_u32(const void* p) {
    uint32_t a;
    asm("{ .reg .u64 t; cvta.to.shared.u64 t, %1; cvt.u32.u64 %0, t; }" : "=r"(a) : "l"(p));
    return a;
}
__device__ __forceinline__ void ldsm4(uint32_t addr, uint32_t r[4]) {
    asm volatile("ldmatrix.sync.aligned.m8n8.x4.shared.b16 {%0,%1,%2,%3}, [%4];"
        : "=r"(r[0]), "=r"(r[1]), "=r"(r[2]), "=r"(r[3]) : "r"(addr));
}
__device__ __forceinline__ void mma16816(float c[4], const uint32_t a[4],
                                         uint32_t b0, uint32_t b1) {
    asm volatile("mma.sync.aligned.m16n8k16.row.col.f32.bf16.bf16.f32 "
        "{%0,%1,%2,%3}, {%4,%5,%6,%7}, {%8,%9}, {%0,%1,%2,%3};"
        : "+f"(c[0]), "+f"(c[1]), "+f"(c[2]), "+f"(c[3])
        : "r"(a[0]), "r"(a[1]), "r"(a[2]), "r"(a[3]), "r"(b0), "r"(b1));
}
#define CPASYNC(dst, src) \
    asm volatile("cp.async.cg.shared.global [%0], [%1], 16;" :: "r"(dst), "l"(src))
#define CP_COMMIT() asm volatile("cp.async.commit_group;" ::: "memory")
#define CP_WAIT(n)  asm volatile("cp.async.wait_group %0;" :: "n"(n) : "memory")

__device__ __forceinline__ float warp_sum(float v) {
#pragma unroll
    for (int o = 16; o > 0; o >>= 1) v += __shfl_xor_sync(0xffffffffu, v, o);
    return v;
}
__device__ __forceinline__ float warp_max(float v) {
#pragma unroll
    for (int o = 16; o > 0; o >>= 1) v = fmaxf(v, __shfl_xor_sync(0xffffffffu, v, o));
    return v;
}

// ---------------------------------------------------------------------------
// Kernel 1: per-(b,c) row scan in smem, 512 threads (16 elems/thread) +
// one proposal per thread.
// ---------------------------------------------------------------------------
__global__ __launch_bounds__(512) void pool_kernel(
    const float* __restrict__ x,
    const void* __restrict__ boxes_raw,
    float* __restrict__ pooled) {
    const int bc = blockIdx.x;
    const int b = bc / C_;
    const float* row = x + (size_t)bc * T_;

    __shared__ float cs[256 * 33];    // element e at (e>>5)*33 + (e&31)
    __shared__ float wsum[16];
    const int t = threadIdx.x;
    const int warp = t >> 5, lane = t & 31;

    for (int j4 = t; j4 < T_ / 4; j4 += 512) {
        float4 v = reinterpret_cast<const float4*>(row)[j4];
        int j = j4 * 4;
        int base = (j >> 5) * 33 + (j & 31);
        cs[base + 0] = v.x; cs[base + 1] = v.y; cs[base + 2] = v.z; cs[base + 3] = v.w;
    }
    __syncthreads();

    // local sequential scan over this thread's 16 elements
    const int base = (t >> 1) * 33 + (t & 1) * 16;
    float run = 0.f;
#pragma unroll
    for (int i = 0; i < 16; i++) { run += cs[base + i]; cs[base + i] = run; }

    // warp-level inclusive scan of per-thread totals
    float incl = run;
#pragma unroll
    for (int o = 1; o < 32; o <<= 1) {
        float up = __shfl_up_sync(0xffffffffu, incl, o);
        if (lane >= o) incl += up;
    }
    if (lane == 31) wsum[warp] = incl;
    __syncthreads();

    float wofs = 0.f;
#pragma unroll
    for (int wv = 0; wv < 16; wv++) wofs += (wv < warp) ? wsum[wv] : 0.f;
    const float ofs = wofs + (incl - run);
#pragma unroll
    for (int i = 0; i < 16; i++) cs[base + i] += ofs;
    __syncthreads();

    const long long* b64all = (const long long*)boxes_raw;
    long long s0 = b64all[0], e0 = b64all[1];
    bool is64 = (s0 >= 0 && s0 < T_ && e0 >= 1 && e0 <= T_ && e0 > s0);

    {
        const int p = t;   // P_ == 512 == blockDim.x
        int s, e;
        if (is64) {
            const long long* bb = b64all + (size_t)b * P_ * 2;
            s = (int)bb[2 * p]; e = (int)bb[2 * p + 1];
        } else {
            const int* bb = ((const int*)boxes_raw) + (size_t)b * P_ * 2;
            s = bb[2 * p]; e = bb[2 * p + 1];
        }
        int ei = e - 1;
        float ge = cs[(ei >> 5) * 33 + (ei & 31)];
        float gs = 0.f;
        if (s > 0) { int si = s - 1; gs = cs[(si >> 5) * 33 + (si & 31)]; }
        pooled[(size_t)bc * P_ + p] = (ge - gs) / (float)(e - s);
    }
}

// ---------------------------------------------------------------------------
// Kernel 2: transpose [B,C,P] -> [B*P, C] with bf16 hi/lo split
// ---------------------------------------------------------------------------
__global__ void transpose_split(const float* __restrict__ pooled,
                                __nv_bfloat16* __restrict__ fH,
                                __nv_bfloat16* __restrict__ fL) {
    __shared__ float t[32][33];
    const int b = blockIdx.z, c0 = blockIdx.x * 32, p0 = blockIdx.y * 32;
    const int tx = threadIdx.x, ty = threadIdx.y;
#pragma unroll
    for (int i = 0; i < 32; i += 8)
        t[ty + i][tx] = pooled[((size_t)(b * C_ + c0 + ty + i)) * P_ + p0 + tx];
    __syncthreads();
#pragma unroll
    for (int i = 0; i < 32; i += 8) {
        size_t row = (size_t)(b * P_ + p0 + ty + i);
        float v = t[tx][ty + i];
        __nv_bfloat16 h = __float2bfloat16_rn(v);
        fH[row * C_ + c0 + tx] = h;
        fL[row * C_ + c0 + tx] = __float2bfloat16_rn(v - __bfloat162float(h));
    }
}

// ---------------------------------------------------------------------------
// Kernel 3: all weight prep fused (W6, W7, packed Whd + bias)
// ---------------------------------------------------------------------------
#define N_W6 (1024 * 512)
#define N_W7 (512 * 1024)
#define N_WHD (128 * 512)
__global__ void prep_all(const float* __restrict__ W6,
                         const float* __restrict__ W7,
                         const float* __restrict__ Wc, const float* __restrict__ bc,
                         const float* __restrict__ Wd, const float* __restrict__ bd,
                         __nv_bfloat16* __restrict__ W6H, __nv_bfloat16* __restrict__ W6L,
                         __nv_bfloat16* __restrict__ W7H, __nv_bfloat16* __restrict__ W7L,
                         __nv_bfloat16* __restrict__ WhdH, __nv_bfloat16* __restrict__ WhdL,
                         float* __restrict__ bhd) {
    const int NT = N_W6 + N_W7 + N_WHD;
    for (int i = blockIdx.x * blockDim.x + threadIdx.x; i < NT; i += gridDim.x * blockDim.x) {
        float v;
        __nv_bfloat16* oh;
        __nv_bfloat16* ol;
        int li;
        if (i < N_W6) { li = i; v = W6[li]; oh = W6H; ol = W6L; }
        else if (i < N_W6 + N_W7) { li = i - N_W6; v = W7[li]; oh = W7H; ol = W7L; }
        else {
            li = i - N_W6 - N_W7;
            int r = li >> 9, k = li & 511;
            v = (r < 30) ? Wc[r * 512 + k] : ((r < 60) ? Wd[(r - 30) * 512 + k] : 0.f);
            oh = WhdH; ol = WhdL;
            if (li < 128) bhd[li] = (li < 30) ? bc[li] : ((li < 60) ? bd[li - 30] : 0.f);
        }
        __nv_bfloat16 h = __float2bfloat16_rn(v);
        oh[li] = h;
        ol[li] = __float2bfloat16_rn(v - __bfloat162float(h));
    }
}

// ---------------------------------------------------------------------------
// mma.sync bf16-split GEMM: C[BM x 128 tile] = act(A[M,K] @ W[N,K]^T + bias)
// 256 threads = 8 warps (2m x 4n), warp tile (BM/2)x32, atoms m16n8k16.
// 3-term split: AH*BH + AH*BL + AL*BH.  cp.async 3-stage, ldmatrix frags.
// MODE 0: relu -> bf16 hi/lo.  MODE 1: relu -> f32 + bf16 hi/lo.
// MODE 2: heads (BM=64): in-register class softmax (quad shfl), writes
//         clsO/detO/cprob directly; wn=0 warps hold cols 0-31, wn=1 32-63.
// ---------------------------------------------------------------------------
#define N_STAGES 3

template <int BM, int MODE>
__global__ __launch_bounds__(256) void gemm_mma(
    const __nv_bfloat16* __restrict__ AH, const __nv_bfloat16* __restrict__ AL,
    const __nv_bfloat16* __restrict__ BH, const __nv_bfloat16* __restrict__ BL,
    const float* __restrict__ bias, int K, int ldC,
    float* __restrict__ outF, __nv_bfloat16* __restrict__ outH,
    __nv_bfloat16* __restrict__ outL,
    float* __restrict__ detO, float* __restrict__ cprob) {

    constexpr int MAC  = BM / 32;            // m-atoms per warp
    constexpr int AGPS = BM * 4;             // A 16B-groups per split per stage
    constexpr int AUN  = (2 * AGPS) / 256;   // A cp.async per thread
    constexpr int ASB  = BM * 64;            // A split bytes
    constexpr int BBASE = 2 * ASB;           // B region offset in stage
    constexpr int STGB = BBASE + 16384;      // stage bytes

    extern __shared__ char smem[];
    const uint32_t sbase = smem_u32(smem);

    const int tid = threadIdx.x;
    const int lane = tid & 31, wid = tid >> 5;
    const int wm = wid >> 2, wn = wid & 3;
    const int m0 = blockIdx.y * BM, n0 = blockIdx.x * 128;

    // ---- global->smem staging indices
    uint32_t offA[AUN], offB[4];
    const __nv_bfloat16* srcA[AUN];
    const __nv_bfloat16* srcB[4];
#pragma unroll
    for (int u = 0; u < AUN; u++) {
        int id = tid + u * 256;
        int split = id / AGPS, g = id % AGPS, row = g >> 2, seg = g & 3;
        uint32_t sw = (uint32_t)(((((row & 1) << 2) + seg) ^ ((row >> 1) & 7)) << 4);
        offA[u] = (uint32_t)(split * ASB + (row >> 1) * 128) + sw;
        srcA[u] = (split ? AL : AH) + (size_t)(m0 + row) * K + seg * 8;
    }
#pragma unroll
    for (int u = 0; u < 4; u++) {
        int id = tid + u * 256;
        int split = id >> 9, g = id & 511, row = g >> 2, seg = g & 3;
        uint32_t sw = (uint32_t)(((((row & 1) << 2) + seg) ^ ((row >> 1) & 7)) << 4);
        offB[u] = (uint32_t)(BBASE + split * 8192 + (row >> 1) * 128) + sw;
        srcB[u] = (split ? BL : BH) + (size_t)(n0 + row) * K + seg * 8;
    }

    // ---- ldmatrix per-lane address components
    const int laneRow = (lane & 7) | (((lane >> 3) & 1) << 3);
    const int segAdd = (lane >> 4) & 1;
    uint32_t pA1[MAC]; int pA2[MAC], pA3[MAC];
#pragma unroll
    for (int ma = 0; ma < MAC; ma++) {
        int row = wm * (BM / 2) + ma * 16 + laneRow;
        pA1[ma] = (uint32_t)((row >> 1) * 128);
        pA2[ma] = (row & 1) << 2;
        pA3[ma] = (row >> 1) & 7;
    }
    uint32_t pB1[2]; int pB2[2], pB3[2];
#pragma unroll
    for (int nb = 0; nb < 2; nb++) {
        int row = wn * 32 + nb * 16 + laneRow;
        pB1[nb] = (uint32_t)((row >> 1) * 128);
        pB2[nb] = (row & 1) << 2;
        pB3[nb] = (row >> 1) & 7;
    }

    float acc[MAC][4][4];
#pragma unroll
    for (int i = 0; i < MAC; i++)
#pragma unroll
        for (int j = 0; j < 4; j++)
#pragma unroll
            for (int q = 0; q < 4; q++) acc[i][j][q] = 0.f;

    const int NIT = K >> 5;

    // prologue: stages 0 and 1
#pragma unroll
    for (int u = 0; u < AUN; u++) CPASYNC(sbase + offA[u], srcA[u]);
#pragma unroll
    for (int u = 0; u < 4; u++) CPASYNC(sbase + offB[u], srcB[u]);
    CP_COMMIT();
    if (NIT > 1) {
        const uint32_t sb = sbase + STGB;
#pragma unroll
        for (int u = 0; u < AUN; u++) CPASYNC(sb + offA[u], srcA[u] + 32);
#pragma unroll
        for (int u = 0; u < 4; u++) CPASYNC(sb + offB[u], srcB[u] + 32);
        CP_COMMIT();
    }

    int st = 0, ld = 2;
    for (int it = 0; it < NIT; it++) {
        if (it + 1 < NIT) { CP_WAIT(1); } else { CP_WAIT(0); }
        __syncthreads();

        if (it + 2 < NIT) {
            const int kpos = (it + 2) << 5;
            const uint32_t sb = sbase + ld * STGB;
#pragma unroll
            for (int u = 0; u < AUN; u++) CPASYNC(sb + offA[u], srcA[u] + kpos);
#pragma unroll
            for (int u = 0; u < 4; u++) CPASYNC(sb + offB[u], srcB[u] + kpos);
            CP_COMMIT();
        }

        const uint32_t stb = sbase + st * STGB;
#pragma unroll
        for (int ks = 0; ks < 2; ks++) {
            uint32_t aH[MAC][4], aL[MAC][4];
#pragma unroll
            for (int ma = 0; ma < MAC; ma++) {
                uint32_t swz = (uint32_t)(((pA2[ma] + ks * 2 + segAdd) ^ pA3[ma]) << 4);
                ldsm4(stb + pA1[ma] + swz, aH[ma]);
                ldsm4(stb + ASB + pA1[ma] + swz, aL[ma]);
            }
            uint32_t bH[2][4], bL[2][4];
#pragma unroll
            for (int nb = 0; nb < 2; nb++) {
                uint32_t swz = (uint32_t)(((pB2[nb] + ks * 2 + segAdd) ^ pB3[nb]) << 4);
                ldsm4(stb + BBASE + pB1[nb] + swz, bH[nb]);
                ldsm4(stb + BBASE + 8192 + pB1[nb] + swz, bL[nb]);
            }
#pragma unroll
            for (int ma = 0; ma < MAC; ma++)
#pragma unroll
                for (int na = 0; na < 4; na++) {
                    uint32_t b0h = bH[na >> 1][na & 1], b1h = bH[na >> 1][2 + (na & 1)];
                    uint32_t b0l = bL[na >> 1][na & 1], b1l = bL[na >> 1][2 + (na & 1)];
                    mma16816(acc[ma][na], aH[ma], b0h, b1h);
                    mma16816(acc[ma][na], aH[ma], b0l, b1l);
                    mma16816(acc[ma][na], aL[ma], b0h, b1h);
                }
        }
        st = (st + 1 == N_STAGES) ? 0 : st + 1;
        ld = (ld + 1 == N_STAGES) ? 0 : ld + 1;
    }

    // ---- epilogue
    const int tr = lane >> 2, tc = (lane & 3) * 2;

    if (MODE == 2) {
        // heads: wn=0 holds cols 0..31 (class 0..29 + det 0,1);
        //        wn=1 holds cols 32..63 (det 2..29 + pad). wn>=2: all pad.
        if (wn <= 1) {
#pragma unroll
            for (int ma = 0; ma < MAC; ma++) {
                const int r0 = m0 + wm * (BM / 2) + ma * 16 + tr;
                const int r1 = r0 + 8;
                float v0[8], v1[8];
#pragma unroll
                for (int na = 0; na < 4; na++) {
                    const int col = wn * 32 + na * 8 + tc;
                    const float b0 = bias[col], b1 = bias[col + 1];
                    v0[na * 2 + 0] = acc[ma][na][0] + b0;
                    v0[na * 2 + 1] = acc[ma][na][1] + b1;
                    v1[na * 2 + 0] = acc[ma][na][2] + b0;
                    v1[na * 2 + 1] = acc[ma][na][3] + b1;
                }
                if (wn == 0) {
                    float mx0 = -INFINITY, mx1 = -INFINITY;
#pragma unroll
                    for (int j = 0; j < 8; j++) {
                        const int col = (j >> 1) * 8 + tc + (j & 1);
                        if (col < 30) { mx0 = fmaxf(mx0, v0[j]); mx1 = fmaxf(mx1, v1[j]); }
                    }
                    mx0 = fmaxf(mx0, __shfl_xor_sync(0xffffffffu, mx0, 1));
                    mx0 = fmaxf(mx0, __shfl_xor_sync(0xffffffffu, mx0, 2));
                    mx1 = fmaxf(mx1, __shfl_xor_sync(0xffffffffu, mx1, 1));
                    mx1 = fmaxf(mx1, __shfl_xor_sync(0xffffffffu, mx1, 2));
                    float e0[8], e1[8], s0 = 0.f, s1 = 0.f;
#pragma unroll
                    for (int j = 0; j < 8; j++) {
                        const int col = (j >> 1) * 8 + tc + (j & 1);
                        if (col < 30) {
                            e0[j] = expf(v0[j] - mx0); s0 += e0[j];
                            e1[j] = expf(v1[j] - mx1); s1 += e1[j];
                        } else { e0[j] = 0.f; e1[j] = 0.f; }
                    }
                    s0 += __shfl_xor_sync(0xffffffffu, s0, 1);
                    s0 += __shfl_xor_sync(0xffffffffu, s0, 2);
                    s1 += __shfl_xor_sync(0xffffffffu, s1, 1);
                    s1 += __shfl_xor_sync(0xffffffffu, s1, 2);
                    const float i0 = 1.f / s0, i1 = 1.f / s1;
#pragma unroll
                    for (int na = 0; na < 4; na++) {
                        const int col = na * 8 + tc;
                        if (col < 30) {
                            *(float2*)(outF + (size_t)r0 * K_ + col) =
                                make_float2(v0[na * 2], v0[na * 2 + 1]);
                            *(float2*)(outF + (size_t)r1 * K_ + col) =
                                make_float2(v1[na * 2], v1[na * 2 + 1]);
                            *(float2*)(cprob + (size_t)r0 * K_ + col) =
                                make_float2(e0[na * 2] * i0, e0[na * 2 + 1] * i0);
                            *(float2*)(cprob + (size_t)r1 * K_ + col) =
                                make_float2(e1[na * 2] * i1, e1[na * 2 + 1] * i1);
                        } else {          // col == 30: det logits 0,1
                            *(float2*)(detO + (size_t)r0 * K_ + 0) =
                                make_float2(v0[na * 2], v0[na * 2 + 1]);
                            *(float2*)(detO + (size_t)r1 * K_ + 0) =
                                make_float2(v1[na * 2], v1[na * 2 + 1]);
                        }
                    }
                } else {  // wn == 1: det logits 2..29 at cols 32..59
#pragma unroll
                    for (int na = 0; na < 4; na++) {
                        const int col = 32 + na * 8 + tc;
                        if (col < 60) {
                            *(float2*)(detO + (size_t)r0 * K_ + (col - 30)) =
                                make_float2(v0[na * 2], v0[na * 2 + 1]);
                            *(float2*)(detO + (size_t)r1 * K_ + (col - 30)) =
                                make_float2(v1[na * 2], v1[na * 2 + 1]);
                        }
                    }
                }
            }
        }
        return;
    }

#pragma unroll
    for (int ma = 0; ma < MAC; ma++) {
        const int r0 = m0 + wm * (BM / 2) + ma * 16 + tr;
#pragma unroll
        for (int na = 0; na < 4; na++) {
            const int col = n0 + wn * 32 + na * 8 + tc;
            const float b0 = bias[col], b1 = bias[col + 1];
            float v00 = fmaxf(acc[ma][na][0] + b0, 0.f), v01 = fmaxf(acc[ma][na][1] + b1, 0.f);
            float v10 = fmaxf(acc[ma][na][2] + b0, 0.f), v11 = fmaxf(acc[ma][na][3] + b1, 0.f);
            if (MODE == 1) {
                *(float2*)(outF + (size_t)r0 * ldC + col) = make_float2(v00, v01);
                *(float2*)(outF + (size_t)(r0 + 8) * ldC + col) = make_float2(v10, v11);
            }
            __nv_bfloat162 h0, h1, l0, l1;
            h0.x = __float2bfloat16_rn(v00); h0.y = __float2bfloat16_rn(v01);
            h1.x = __float2bfloat16_rn(v10); h1.y = __float2bfloat16_rn(v11);
            l0.x = __float2bfloat16_rn(v00 - __bfloat162float(h0.x));
            l0.y = __float2bfloat16_rn(v01 - __bfloat162float(h0.y));
            l1.x = __float2bfloat16_rn(v10 - __bfloat162float(h1.x));
            l1.y = __float2bfloat16_rn(v11 - __bfloat162float(h1.y));
            *(__nv_bfloat162*)(outH + (size_t)r0 * ldC + col) = h0;
            *(__nv_bfloat162*)(outH + (size_t)(r0 + 8) * ldC + col) = h1;
            *(__nv_bfloat162*)(outL + (size_t)r0 * ldC + col) = l0;
            *(__nv_bfloat162*)(outL + (size_t)(r0 + 8) * ldC + col) = l1;
        }
    }
}

// ---------------------------------------------------------------------------
// fused det-softmax + joint + video: one block per (b,k)
// ---------------------------------------------------------------------------
__global__ __launch_bounds__(256) void detjoint_kernel(
    const float* __restrict__ detL, const float* __restrict__ cprob,
    float* __restrict__ joint, float* __restrict__ video) {
    const int bk = blockIdx.x;
    const int b = bk / K_, k = bk % K_;
    const int tid = threadIdx.x;
    const int warp = tid >> 5, lane = tid & 31;
    __shared__ float red[8];

    const size_t i0 = ((size_t)(b * P_ + tid)) * K_ + k;
    const size_t i1 = ((size_t)(b * P_ + tid + 256)) * K_ + k;
    const float v0 = detL[i0], v1 = detL[i1];

    float mx = warp_max(fmaxf(v0, v1));
    if (lane == 0) red[warp] = mx;
    __syncthreads();
    float bm = red[0];
#pragma unroll
    for (int i = 1; i < 8; i++) bm = fmaxf(bm, red[i]);

    const float e0 = expf(v0 - bm), e1 = expf(v1 - bm);
    float sm = warp_sum(e0 + e1);
    __syncthreads();
    if (lane == 0) red[warp] = sm;
    __syncthreads();
    float bs = 0.f;
#pragma unroll
    for (int i = 0; i < 8; i++) bs += red[i];
    const float inv = 1.f / bs;

    const float j0 = cprob[i0] * e0 * inv;
    const float j1 = cprob[i1] * e1 * inv;
    joint[i0] = j0;
    joint[i1] = j1;
    float js = warp_sum(j0 + j1);
    __syncthreads();
    if (lane == 0) red[warp] = js;
    __syncthreads();
    if (tid == 0) {
        float tot = 0.f;
#pragma unroll
        for (int i = 0; i < 8; i++) tot += red[i];
        video[bk] = tot;
    }
}

// ---------------------------------------------------------------------------
extern "C" void kernel_launch(void* const* d_in, const int* in_sizes, int n_in,
                              void* d_out, int out_size) {
    const float* x  = (const float*)d_in[0];
    const void*  bx = d_in[1];
    const float* W6 = (const float*)d_in[2];
    const float* b6 = (const float*)d_in[3];
    const float* W7 = (const float*)d_in[4];
    const float* b7 = (const float*)d_in[5];
    const float* Wc = (const float*)d_in[6];
    const float* bc = (const float*)d_in[7];
    const float* Wd = (const float*)d_in[8];
    const float* bd = (const float*)d_in[9];
    float* out = (float*)d_out;

    float *pooled, *bhd, *cprob;
    __nv_bfloat16 *fH, *fL, *W6H, *W6L, *W7H, *W7L, *h6H, *h6L, *h7H, *h7L, *WhdH, *WhdL;
    cudaGetSymbolAddress((void**)&pooled, g_pooled);
    cudaGetSymbolAddress((void**)&fH, g_fH);   cudaGetSymbolAddress((void**)&fL, g_fL);
    cudaGetSymbolAddress((void**)&W6H, g_W6H); cudaGetSymbolAddress((void**)&W6L, g_W6L);
    cudaGetSymbolAddress((void**)&W7H, g_W7H); cudaGetSymbolAddress((void**)&W7L, g_W7L);
    cudaGetSymbolAddress((void**)&h6H, g_h6H); cudaGetSymbolAddress((void**)&h6L, g_h6L);
    cudaGetSymbolAddress((void**)&h7H, g_h7H); cudaGetSymbolAddress((void**)&h7L, g_h7L);
    cudaGetSymbolAddress((void**)&WhdH, g_WhdH); cudaGetSymbolAddress((void**)&WhdL, g_WhdL);
    cudaGetSymbolAddress((void**)&bhd, g_bhd);
    cudaGetSymbolAddress((void**)&cprob, g_cprob);

    float* h7    = out + H7_OFF;
    float* clsO  = out + CLS_OFF;
    float* detO  = out + DET_OFF;
    float* joint = out + JOINT_OFF;
    float* video = out + VIDEO_OFF;

    const int SMEM128 = N_STAGES * (128 * 128 + 16384);   // 98304
    const int SMEM64  = N_STAGES * (64 * 128 + 16384);    // 73728
    cudaFuncSetAttribute((gemm_mma<128, 0>), cudaFuncAttributeMaxDynamicSharedMemorySize, SMEM128);
    cudaFuncSetAttribute((gemm_mma<64, 1>),  cudaFuncAttributeMaxDynamicSharedMemorySize, SMEM64);
    cudaFuncSetAttribute((gemm_mma<64, 2>),  cudaFuncAttributeMaxDynamicSharedMemorySize, SMEM64);

    // 1. pooled [B*C, P]  (512 threads: 16 elems/thread scan, 1 proposal/thread)
    pool_kernel<<<B_ * C_, 512>>>(x, bx, pooled);
    // 2. feats bf16 hi/lo [M, C]
    transpose_split<<<dim3(C_ / 32, P_ / 32, B_), dim3(32, 8)>>>(pooled, fH, fL);
    // 3. all weight prep in one launch
    prep_all<<<592, 256>>>(W6, W7, Wc, bc, Wd, bd, W6H, W6L, W7H, W7L, WhdH, WhdL, bhd);

    // 4. h6 = relu(feats @ W6^T + b6) : M=4096, N=1024, K=512  (BM=128, 256 CTAs)
    gemm_mma<128, 0><<<dim3(8, 32), 256, SMEM128>>>(fH, fL, W6H, W6L, b6, 512, 1024,
                                                    nullptr, h6H, h6L, nullptr, nullptr);
    // 5. h7 = relu(h6 @ W7^T + b7) : M=4096, N=512, K=1024  (BM=64, 256 CTAs)
    gemm_mma<64, 1><<<dim3(4, 64), 256, SMEM64>>>(h6H, h6L, W7H, W7L, b7, 1024, 512,
                                                  h7, h7H, h7L, nullptr, nullptr);
    // 6. heads + fused class softmax: writes clsO/detO/cprob directly (BM=64, 64 CTAs)
    gemm_mma<64, 2><<<dim3(1, 64), 256, SMEM64>>>(h7H, h7L, WhdH, WhdL, bhd, 512, 0,
                                                  clsO, nullptr, nullptr, detO, cprob);

    // 7. fused det softmax + joint + video
    detjoint_kernel<<<B_ * K_, 256>>>(detO, cprob, joint, video);
}

// round 16
// speedup vs baseline: 1.0603x; 1.0126x over previous
#include <cuda_runtime.h>
#include <cuda_bf16.h>
#include <math.h>
#include <stdint.h>

#define B_ 8
#define C_ 512
#define T_ 8192
#define P_ 512
#define K_ 30
#define M_ (B_ * P_)          // 4096 rows through the MLP

// output layout (concatenated tuple, fp32)
#define VIDEO_OFF 0
#define JOINT_OFF (VIDEO_OFF + B_ * K_)                 // 240
#define CLS_OFF   (JOINT_OFF + M_ * K_)                 // 123120
#define DET_OFF   (CLS_OFF + M_ * K_)                   // 246000
#define H7_OFF    (DET_OFF + M_ * K_)                   // 368880

// ------------------------- scratch (no cudaMalloc) -------------------------
__device__ float          g_pooled[B_ * C_ * P_];        // [B*C, P]
__device__ __nv_bfloat16  g_fH[M_ * C_],   g_fL[M_ * C_];
__device__ __nv_bfloat16  g_W6H[1024 * 512], g_W6L[1024 * 512];
__device__ __nv_bfloat16  g_W7H[512 * 1024], g_W7L[512 * 1024];
__device__ __nv_bfloat16  g_h6H[M_ * 1024],  g_h6L[M_ * 1024];
__device__ __nv_bfloat16  g_h7H[M_ * 512],   g_h7L[M_ * 512];
__device__ __nv_bfloat16  g_WhdH[128 * 512], g_WhdL[128 * 512];
__device__ float          g_bhd[128];
__device__ float          g_cprob[M_ * K_];

// ------------------------- helpers -------------------------
__device__ __forceinline__ uint32_t smem_u32(const void* p) {
    uint32_t a;
    asm("{ .reg .u64 t; cvta.to.shared.u64 t, %1; cvt.u32.u64 %0, t; }" : "=r"(a) : "l"(p));
    return a;
}
__device__ __forceinline__ void ldsm4(uint32_t addr, uint32_t r[4]) {
    asm volatile("ldmatrix.sync.aligned.m8n8.x4.shared.b16 {%0,%1,%2,%3}, [%4];"
        : "=r"(r[0]), "=r"(r[1]), "=r"(r[2]), "=r"(r[3]) : "r"(addr));
}
__device__ __forceinline__ void mma16816(float c[4], const uint32_t a[4],
                                         uint32_t b0, uint32_t b1) {
    asm volatile("mma.sync.aligned.m16n8k16.row.col.f32.bf16.bf16.f32 "
        "{%0,%1,%2,%3}, {%4,%5,%6,%7}, {%8,%9}, {%0,%1,%2,%3};"
        : "+f"(c[0]), "+f"(c[1]), "+f"(c[2]), "+f"(c[3])
        : "r"(a[0]), "r"(a[1]), "r"(a[2]), "r"(a[3]), "r"(b0), "r"(b1));
}
#define CPASYNC(dst, src) \
    asm volatile("cp.async.cg.shared.global [%0], [%1], 16;" :: "r"(dst), "l"(src))
#define CP_COMMIT() asm volatile("cp.async.commit_group;" ::: "memory")
#define CP_WAIT(n)  asm volatile("cp.async.wait_group %0;" :: "n"(n) : "memory")

__device__ __forceinline__ float warp_sum(float v) {
#pragma unroll
    for (int o = 16; o > 0; o >>= 1) v += __shfl_xor_sync(0xffffffffu, v, o);
    return v;
}
__device__ __forceinline__ float warp_max(float v) {
#pragma unroll
    for (int o = 16; o > 0; o >>= 1) v = fmaxf(v, __shfl_xor_sync(0xffffffffu, v, o));
    return v;
}

// ---------------------------------------------------------------------------
// Kernel 1: per-(b,c) row scan in smem, 512 threads (16 elems/thread) +
// one proposal per thread.
// ---------------------------------------------------------------------------
__global__ __launch_bounds__(512) void pool_kernel(
    const float* __restrict__ x,
    const void* __restrict__ boxes_raw,
    float* __restrict__ pooled) {
    const int bc = blockIdx.x;
    const int b = bc / C_;
    const float* row = x + (size_t)bc * T_;

    __shared__ float cs[256 * 33];    // element e at (e>>5)*33 + (e&31)
    __shared__ float wsum[16];
    const int t = threadIdx.x;
    const int warp = t >> 5, lane = t & 31;

    for (int j4 = t; j4 < T_ / 4; j4 += 512) {
        float4 v = reinterpret_cast<const float4*>(row)[j4];
        int j = j4 * 4;
        int base = (j >> 5) * 33 + (j & 31);
        cs[base + 0] = v.x; cs[base + 1] = v.y; cs[base + 2] = v.z; cs[base + 3] = v.w;
    }
    __syncthreads();

    const int base = (t >> 1) * 33 + (t & 1) * 16;
    float run = 0.f;
#pragma unroll
    for (int i = 0; i < 16; i++) { run += cs[base + i]; cs[base + i] = run; }

    float incl = run;
#pragma unroll
    for (int o = 1; o < 32; o <<= 1) {
        float up = __shfl_up_sync(0xffffffffu, incl, o);
        if (lane >= o) incl += up;
    }
    if (lane == 31) wsum[warp] = incl;
    __syncthreads();

    float wofs = 0.f;
#pragma unroll
    for (int wv = 0; wv < 16; wv++) wofs += (wv < warp) ? wsum[wv] : 0.f;
    const float ofs = wofs + (incl - run);
#pragma unroll
    for (int i = 0; i < 16; i++) cs[base + i] += ofs;
    __syncthreads();

    const long long* b64all = (const long long*)boxes_raw;
    long long s0 = b64all[0], e0 = b64all[1];
    bool is64 = (s0 >= 0 && s0 < T_ && e0 >= 1 && e0 <= T_ && e0 > s0);

    {
        const int p = t;   // P_ == 512 == blockDim.x
        int s, e;
        if (is64) {
            const long long* bb = b64all + (size_t)b * P_ * 2;
            s = (int)bb[2 * p]; e = (int)bb[2 * p + 1];
        } else {
            const int* bb = ((const int*)boxes_raw) + (size_t)b * P_ * 2;
            s = bb[2 * p]; e = bb[2 * p + 1];
        }
        int ei = e - 1;
        float ge = cs[(ei >> 5) * 33 + (ei & 31)];
        float gs = 0.f;
        if (s > 0) { int si = s - 1; gs = cs[(si >> 5) * 33 + (si & 31)]; }
        pooled[(size_t)bc * P_ + p] = (ge - gs) / (float)(e - s);
    }
}

// ---------------------------------------------------------------------------
// Kernel 2: transpose+split (blocks 0..2047) fused with weight prep
// (blocks 2048..2639). Both independent; co-scheduled in one launch.
// ---------------------------------------------------------------------------
#define N_W6 (1024 * 512)
#define N_W7 (512 * 1024)
#define N_WHD (128 * 512)
#define TRN_BLOCKS 2048          // (C/32)*(P/32)*B = 16*16*8
#define PREP_BLOCKS 592

__global__ __launch_bounds__(256) void transprep_kernel(
    const float* __restrict__ pooled,
    __nv_bfloat16* __restrict__ fH,
    __nv_bfloat16* __restrict__ fL,
    const float* __restrict__ W6,
    const float* __restrict__ W7,
    const float* __restrict__ Wc, const float* __restrict__ bc,
    const float* __restrict__ Wd, const float* __restrict__ bd,
    __nv_bfloat16* __restrict__ W6H, __nv_bfloat16* __restrict__ W6L,
    __nv_bfloat16* __restrict__ W7H, __nv_bfloat16* __restrict__ W7L,
    __nv_bfloat16* __restrict__ WhdH, __nv_bfloat16* __restrict__ WhdL,
    float* __restrict__ bhd) {
    if (blockIdx.x >= TRN_BLOCKS) {
        const int NT = N_W6 + N_W7 + N_WHD;
        const int base = (blockIdx.x - TRN_BLOCKS) * 256 + threadIdx.x;
        const int stride = PREP_BLOCKS * 256;
        for (int i = base; i < NT; i += stride) {
            float v;
            __nv_bfloat16* oh;
            __nv_bfloat16* ol;
            int li;
            if (i < N_W6) { li = i; v = W6[li]; oh = W6H; ol = W6L; }
            else if (i < N_W6 + N_W7) { li = i - N_W6; v = W7[li]; oh = W7H; ol = W7L; }
            else {
                li = i - N_W6 - N_W7;
                int r = li >> 9, k = li & 511;
                v = (r < 30) ? Wc[r * 512 + k] : ((r < 60) ? Wd[(r - 30) * 512 + k] : 0.f);
                oh = WhdH; ol = WhdL;
                if (li < 128) bhd[li] = (li < 30) ? bc[li] : ((li < 60) ? bd[li - 30] : 0.f);
            }
            __nv_bfloat16 h = __float2bfloat16_rn(v);
            oh[li] = h;
            ol[li] = __float2bfloat16_rn(v - __bfloat162float(h));
        }
        return;
    }

    // ---- transpose branch: [B,C,P] -> [B*P, C] with bf16 hi/lo split
    __shared__ float t[32][33];
    const int gb = blockIdx.x;
    const int cblk = gb & 15, pblk = (gb >> 4) & 15, b = gb >> 8;
    const int c0 = cblk * 32, p0 = pblk * 32;
    const int tx = threadIdx.x & 31, ty = threadIdx.x >> 5;
#pragma unroll
    for (int i = 0; i < 32; i += 8)
        t[ty + i][tx] = pooled[((size_t)(b * C_ + c0 + ty + i)) * P_ + p0 + tx];
    __syncthreads();
#pragma unroll
    for (int i = 0; i < 32; i += 8) {
        size_t row = (size_t)(b * P_ + p0 + ty + i);
        float v = t[tx][ty + i];
        __nv_bfloat16 h = __float2bfloat16_rn(v);
        fH[row * C_ + c0 + tx] = h;
        fL[row * C_ + c0 + tx] = __float2bfloat16_rn(v - __bfloat162float(h));
    }
}

// ---------------------------------------------------------------------------
// mma.sync bf16-split GEMM: C[BM x 128 tile] = act(A[M,K] @ W[N,K]^T + bias)
// 256 threads = 8 warps (2m x 4n), warp tile (BM/2)x32, atoms m16n8k16.
// 3-term split: AH*BH + AH*BL + AL*BH.  cp.async 3-stage, ldmatrix frags.
// MODE 0: relu -> bf16 hi/lo.  MODE 1: relu -> f32 + bf16 hi/lo.
// MODE 2: heads (BM=64): in-register class softmax (quad shfl), writes
//         clsO/detO/cprob directly; wn=0 warps hold cols 0-31, wn=1 32-63.
// ---------------------------------------------------------------------------
#define N_STAGES 3

template <int BM, int MODE>
__global__ __launch_bounds__(256) void gemm_mma(
    const __nv_bfloat16* __restrict__ AH, const __nv_bfloat16* __restrict__ AL,
    const __nv_bfloat16* __restrict__ BH, const __nv_bfloat16* __restrict__ BL,
    const float* __restrict__ bias, int K, int ldC,
    float* __restrict__ outF, __nv_bfloat16* __restrict__ outH,
    __nv_bfloat16* __restrict__ outL,
    float* __restrict__ detO, float* __restrict__ cprob) {

    constexpr int MAC  = BM / 32;            // m-atoms per warp
    constexpr int AGPS = BM * 4;             // A 16B-groups per split per stage
    constexpr int AUN  = (2 * AGPS) / 256;   // A cp.async per thread
    constexpr int ASB  = BM * 64;            // A split bytes
    constexpr int BBASE = 2 * ASB;           // B region offset in stage
    constexpr int STGB = BBASE + 16384;      // stage bytes

    extern __shared__ char smem[];
    const uint32_t sbase = smem_u32(smem);

    const int tid = threadIdx.x;
    const int lane = tid & 31, wid = tid >> 5;
    const int wm = wid >> 2, wn = wid & 3;
    const int m0 = blockIdx.y * BM, n0 = blockIdx.x * 128;

    // ---- global->smem staging indices
    uint32_t offA[AUN], offB[4];
    const __nv_bfloat16* srcA[AUN];
    const __nv_bfloat16* srcB[4];
#pragma unroll
    for (int u = 0; u < AUN; u++) {
        int id = tid + u * 256;
        int split = id / AGPS, g = id % AGPS, row = g >> 2, seg = g & 3;
        uint32_t sw = (uint32_t)(((((row & 1) << 2) + seg) ^ ((row >> 1) & 7)) << 4);
        offA[u] = (uint32_t)(split * ASB + (row >> 1) * 128) + sw;
        srcA[u] = (split ? AL : AH) + (size_t)(m0 + row) * K + seg * 8;
    }
#pragma unroll
    for (int u = 0; u < 4; u++) {
        int id = tid + u * 256;
        int split = id >> 9, g = id & 511, row = g >> 2, seg = g & 3;
        uint32_t sw = (uint32_t)(((((row & 1) << 2) + seg) ^ ((row >> 1) & 7)) << 4);
        offB[u] = (uint32_t)(BBASE + split * 8192 + (row >> 1) * 128) + sw;
        srcB[u] = (split ? BL : BH) + (size_t)(n0 + row) * K + seg * 8;
    }

    // ---- ldmatrix per-lane address components
    const int laneRow = (lane & 7) | (((lane >> 3) & 1) << 3);
    const int segAdd = (lane >> 4) & 1;
    uint32_t pA1[MAC]; int pA2[MAC], pA3[MAC];
#pragma unroll
    for (int ma = 0; ma < MAC; ma++) {
        int row = wm * (BM / 2) + ma * 16 + laneRow;
        pA1[ma] = (uint32_t)((row >> 1) * 128);
        pA2[ma] = (row & 1) << 2;
        pA3[ma] = (row >> 1) & 7;
    }
    uint32_t pB1[2]; int pB2[2], pB3[2];
#pragma unroll
    for (int nb = 0; nb < 2; nb++) {
        int row = wn * 32 + nb * 16 + laneRow;
        pB1[nb] = (uint32_t)((row >> 1) * 128);
        pB2[nb] = (row & 1) << 2;
        pB3[nb] = (row >> 1) & 7;
    }

    float acc[MAC][4][4];
#pragma unroll
    for (int i = 0; i < MAC; i++)
#pragma unroll
        for (int j = 0; j < 4; j++)
#pragma unroll
            for (int q = 0; q < 4; q++) acc[i][j][q] = 0.f;

    const int NIT = K >> 5;

    // prologue: stages 0 and 1
#pragma unroll
    for (int u = 0; u < AUN; u++) CPASYNC(sbase + offA[u], srcA[u]);
#pragma unroll
    for (int u = 0; u < 4; u++) CPASYNC(sbase + offB[u], srcB[u]);
    CP_COMMIT();
    if (NIT > 1) {
        const uint32_t sb = sbase + STGB;
#pragma unroll
        for (int u = 0; u < AUN; u++) CPASYNC(sb + offA[u], srcA[u] + 32);
#pragma unroll
        for (int u = 0; u < 4; u++) CPASYNC(sb + offB[u], srcB[u] + 32);
        CP_COMMIT();
    }

    int st = 0, ld = 2;
    for (int it = 0; it < NIT; it++) {
        if (it + 1 < NIT) { CP_WAIT(1); } else { CP_WAIT(0); }
        __syncthreads();

        if (it + 2 < NIT) {
            const int kpos = (it + 2) << 5;
            const uint32_t sb = sbase + ld * STGB;
#pragma unroll
            for (int u = 0; u < AUN; u++) CPASYNC(sb + offA[u], srcA[u] + kpos);
#pragma unroll
            for (int u = 0; u < 4; u++) CPASYNC(sb + offB[u], srcB[u] + kpos);
            CP_COMMIT();
        }

        const uint32_t stb = sbase + st * STGB;
#pragma unroll
        for (int ks = 0; ks < 2; ks++) {
            uint32_t aH[MAC][4], aL[MAC][4];
#pragma unroll
            for (int ma = 0; ma < MAC; ma++) {
                uint32_t swz = (uint32_t)(((pA2[ma] + ks * 2 + segAdd) ^ pA3[ma]) << 4);
                ldsm4(stb + pA1[ma] + swz, aH[ma]);
                ldsm4(stb + ASB + pA1[ma] + swz, aL[ma]);
            }
            uint32_t bH[2][4], bL[2][4];
#pragma unroll
            for (int nb = 0; nb < 2; nb++) {
                uint32_t swz = (uint32_t)(((pB2[nb] + ks * 2 + segAdd) ^ pB3[nb]) << 4);
                ldsm4(stb + BBASE + pB1[nb] + swz, bH[nb]);
                ldsm4(stb + BBASE + 8192 + pB1[nb] + swz, bL[nb]);
            }
#pragma unroll
            for (int ma = 0; ma < MAC; ma++)
#pragma unroll
                for (int na = 0; na < 4; na++) {
                    uint32_t b0h = bH[na >> 1][na & 1], b1h = bH[na >> 1][2 + (na & 1)];
                    uint32_t b0l = bL[na >> 1][na & 1], b1l = bL[na >> 1][2 + (na & 1)];
                    mma16816(acc[ma][na], aH[ma], b0h, b1h);
                    mma16816(acc[ma][na], aH[ma], b0l, b1l);
                    mma16816(acc[ma][na], aL[ma], b0h, b1h);
                }
        }
        st = (st + 1 == N_STAGES) ? 0 : st + 1;
        ld = (ld + 1 == N_STAGES) ? 0 : ld + 1;
    }

    // ---- epilogue
    const int tr = lane >> 2, tc = (lane & 3) * 2;

    if (MODE == 2) {
        // heads: wn=0 holds cols 0..31 (class 0..29 + det 0,1);
        //        wn=1 holds cols 32..63 (det 2..29 + pad). wn>=2: all pad.
        if (wn <= 1) {
#pragma unroll
            for (int ma = 0; ma < MAC; ma++) {
                const int r0 = m0 + wm * (BM / 2) + ma * 16 + tr;
                const int r1 = r0 + 8;
                float v0[8], v1[8];
#pragma unroll
                for (int na = 0; na < 4; na++) {
                    const int col = wn * 32 + na * 8 + tc;
                    const float b0 = bias[col], b1 = bias[col + 1];
                    v0[na * 2 + 0] = acc[ma][na][0] + b0;
                    v0[na * 2 + 1] = acc[ma][na][1] + b1;
                    v1[na * 2 + 0] = acc[ma][na][2] + b0;
                    v1[na * 2 + 1] = acc[ma][na][3] + b1;
                }
                if (wn == 0) {
                    float mx0 = -INFINITY, mx1 = -INFINITY;
#pragma unroll
                    for (int j = 0; j < 8; j++) {
                        const int col = (j >> 1) * 8 + tc + (j & 1);
                        if (col < 30) { mx0 = fmaxf(mx0, v0[j]); mx1 = fmaxf(mx1, v1[j]); }
                    }
                    mx0 = fmaxf(mx0, __shfl_xor_sync(0xffffffffu, mx0, 1));
                    mx0 = fmaxf(mx0, __shfl_xor_sync(0xffffffffu, mx0, 2));
                    mx1 = fmaxf(mx1, __shfl_xor_sync(0xffffffffu, mx1, 1));
                    mx1 = fmaxf(mx1, __shfl_xor_sync(0xffffffffu, mx1, 2));
                    float e0[8], e1[8], s0 = 0.f, s1 = 0.f;
#pragma unroll
                    for (int j = 0; j < 8; j++) {
                        const int col = (j >> 1) * 8 + tc + (j & 1);
                        if (col < 30) {
                            e0[j] = expf(v0[j] - mx0); s0 += e0[j];
                            e1[j] = expf(v1[j] - mx1); s1 += e1[j];
                        } else { e0[j] = 0.f; e1[j] = 0.f; }
                    }
                    s0 += __shfl_xor_sync(0xffffffffu, s0, 1);
                    s0 += __shfl_xor_sync(0xffffffffu, s0, 2);
                    s1 += __shfl_xor_sync(0xffffffffu, s1, 1);
                    s1 += __shfl_xor_sync(0xffffffffu, s1, 2);
                    const float i0 = 1.f / s0, i1 = 1.f / s1;
#pragma unroll
                    for (int na = 0; na < 4; na++) {
                        const int col = na * 8 + tc;
                        if (col < 30) {
                            *(float2*)(outF + (size_t)r0 * K_ + col) =
                                make_float2(v0[na * 2], v0[na * 2 + 1]);
                            *(float2*)(outF + (size_t)r1 * K_ + col) =
                                make_float2(v1[na * 2], v1[na * 2 + 1]);
                            *(float2*)(cprob + (size_t)r0 * K_ + col) =
                                make_float2(e0[na * 2] * i0, e0[na * 2 + 1] * i0);
                            *(float2*)(cprob + (size_t)r1 * K_ + col) =
                                make_float2(e1[na * 2] * i1, e1[na * 2 + 1] * i1);
                        } else {          // col == 30: det logits 0,1
                            *(float2*)(detO + (size_t)r0 * K_ + 0) =
                                make_float2(v0[na * 2], v0[na * 2 + 1]);
                            *(float2*)(detO + (size_t)r1 * K_ + 0) =
                                make_float2(v1[na * 2], v1[na * 2 + 1]);
                        }
                    }
                } else {  // wn == 1: det logits 2..29 at cols 32..59
#pragma unroll
                    for (int na = 0; na < 4; na++) {
                        const int col = 32 + na * 8 + tc;
                        if (col < 60) {
                            *(float2*)(detO + (size_t)r0 * K_ + (col - 30)) =
                                make_float2(v0[na * 2], v0[na * 2 + 1]);
                            *(float2*)(detO + (size_t)r1 * K_ + (col - 30)) =
                                make_float2(v1[na * 2], v1[na * 2 + 1]);
                        }
                    }
                }
            }
        }
        return;
    }

#pragma unroll
    for (int ma = 0; ma < MAC; ma++) {
        const int r0 = m0 + wm * (BM / 2) + ma * 16 + tr;
#pragma unroll
        for (int na = 0; na < 4; na++) {
            const int col = n0 + wn * 32 + na * 8 + tc;
            const float b0 = bias[col], b1 = bias[col + 1];
            float v00 = fmaxf(acc[ma][na][0] + b0, 0.f), v01 = fmaxf(acc[ma][na][1] + b1, 0.f);
            float v10 = fmaxf(acc[ma][na][2] + b0, 0.f), v11 = fmaxf(acc[ma][na][3] + b1, 0.f);
            if (MODE == 1) {
                *(float2*)(outF + (size_t)r0 * ldC + col) = make_float2(v00, v01);
                *(float2*)(outF + (size_t)(r0 + 8) * ldC + col) = make_float2(v10, v11);
            }
            __nv_bfloat162 h0, h1, l0, l1;
            h0.x = __float2bfloat16_rn(v00); h0.y = __float2bfloat16_rn(v01);
            h1.x = __float2bfloat16_rn(v10); h1.y = __float2bfloat16_rn(v11);
            l0.x = __float2bfloat16_rn(v00 - __bfloat162float(h0.x));
            l0.y = __float2bfloat16_rn(v01 - __bfloat162float(h0.y));
            l1.x = __float2bfloat16_rn(v10 - __bfloat162float(h1.x));
            l1.y = __float2bfloat16_rn(v11 - __bfloat162float(h1.y));
            *(__nv_bfloat162*)(outH + (size_t)r0 * ldC + col) = h0;
            *(__nv_bfloat162*)(outH + (size_t)(r0 + 8) * ldC + col) = h1;
            *(__nv_bfloat162*)(outL + (size_t)r0 * ldC + col) = l0;
            *(__nv_bfloat162*)(outL + (size_t)(r0 + 8) * ldC + col) = l1;
        }
    }
}

// ---------------------------------------------------------------------------
// fused det-softmax + joint + video: one block per (b,k)
// ---------------------------------------------------------------------------
__global__ __launch_bounds__(256) void detjoint_kernel(
    const float* __restrict__ detL, const float* __restrict__ cprob,
    float* __restrict__ joint, float* __restrict__ video) {
    const int bk = blockIdx.x;
    const int b = bk / K_, k = bk % K_;
    const int tid = threadIdx.x;
    const int warp = tid >> 5, lane = tid & 31;
    __shared__ float red[8];

    const size_t i0 = ((size_t)(b * P_ + tid)) * K_ + k;
    const size_t i1 = ((size_t)(b * P_ + tid + 256)) * K_ + k;
    const float v0 = detL[i0], v1 = detL[i1];

    float mx = warp_max(fmaxf(v0, v1));
    if (lane == 0) red[warp] = mx;
    __syncthreads();
    float bm = red[0];
#pragma unroll
    for (int i = 1; i < 8; i++) bm = fmaxf(bm, red[i]);

    const float e0 = expf(v0 - bm), e1 = expf(v1 - bm);
    float sm = warp_sum(e0 + e1);
    __syncthreads();
    if (lane == 0) red[warp] = sm;
    __syncthreads();
    float bs = 0.f;
#pragma unroll
    for (int i = 0; i < 8; i++) bs += red[i];
    const float inv = 1.f / bs;

    const float j0 = cprob[i0] * e0 * inv;
    const float j1 = cprob[i1] * e1 * inv;
    joint[i0] = j0;
    joint[i1] = j1;
    float js = warp_sum(j0 + j1);
    __syncthreads();
    if (lane == 0) red[warp] = js;
    __syncthreads();
    if (tid == 0) {
        float tot = 0.f;
#pragma unroll
        for (int i = 0; i < 8; i++) tot += red[i];
        video[bk] = tot;
    }
}

// ---------------------------------------------------------------------------
extern "C" void kernel_launch(void* const* d_in, const int* in_sizes, int n_in,
                              void* d_out, int out_size) {
    const float* x  = (const float*)d_in[0];
    const void*  bx = d_in[1];
    const float* W6 = (const float*)d_in[2];
    const float* b6 = (const float*)d_in[3];
    const float* W7 = (const float*)d_in[4];
    const float* b7 = (const float*)d_in[5];
    const float* Wc = (const float*)d_in[6];
    const float* bc = (const float*)d_in[7];
    const float* Wd = (const float*)d_in[8];
    const float* bd = (const float*)d_in[9];
    float* out = (float*)d_out;

    float *pooled, *bhd, *cprob;
    __nv_bfloat16 *fH, *fL, *W6H, *W6L, *W7H, *W7L, *h6H, *h6L, *h7H, *h7L, *WhdH, *WhdL;
    cudaGetSymbolAddress((void**)&pooled, g_pooled);
    cudaGetSymbolAddress((void**)&fH, g_fH);   cudaGetSymbolAddress((void**)&fL, g_fL);
    cudaGetSymbolAddress((void**)&W6H, g_W6H); cudaGetSymbolAddress((void**)&W6L, g_W6L);
    cudaGetSymbolAddress((void**)&W7H, g_W7H); cudaGetSymbolAddress((void**)&W7L, g_W7L);
    cudaGetSymbolAddress((void**)&h6H, g_h6H); cudaGetSymbolAddress((void**)&h6L, g_h6L);
    cudaGetSymbolAddress((void**)&h7H, g_h7H); cudaGetSymbolAddress((void**)&h7L, g_h7L);
    cudaGetSymbolAddress((void**)&WhdH, g_WhdH); cudaGetSymbolAddress((void**)&WhdL, g_WhdL);
    cudaGetSymbolAddress((void**)&bhd, g_bhd);
    cudaGetSymbolAddress((void**)&cprob, g_cprob);

    float* h7    = out + H7_OFF;
    float* clsO  = out + CLS_OFF;
    float* detO  = out + DET_OFF;
    float* joint = out + JOINT_OFF;
    float* video = out + VIDEO_OFF;

    const int SMEM128 = N_STAGES * (128 * 128 + 16384);   // 98304
    const int SMEM64  = N_STAGES * (64 * 128 + 16384);    // 73728
    cudaFuncSetAttribute((gemm_mma<128, 0>), cudaFuncAttributeMaxDynamicSharedMemorySize, SMEM128);
    cudaFuncSetAttribute((gemm_mma<64, 1>),  cudaFuncAttributeMaxDynamicSharedMemorySize, SMEM64);
    cudaFuncSetAttribute((gemm_mma<64, 2>),  cudaFuncAttributeMaxDynamicSharedMemorySize, SMEM64);

    // 1. pooled [B*C, P]  (512 threads: 16 elems/thread scan, 1 proposal/thread)
    pool_kernel<<<B_ * C_, 512>>>(x, bx, pooled);
    // 2. transpose+split fused with weight prep (independent work, one launch)
    transprep_kernel<<<TRN_BLOCKS + PREP_BLOCKS, 256>>>(
        pooled, fH, fL, W6, W7, Wc, bc, Wd, bd,
        W6H, W6L, W7H, W7L, WhdH, WhdL, bhd);

    // 3. h6 = relu(feats @ W6^T + b6) : M=4096, N=1024, K=512  (BM=128, 256 CTAs)
    gemm_mma<128, 0><<<dim3(8, 32), 256, SMEM128>>>(fH, fL, W6H, W6L, b6, 512, 1024,
                                                    nullptr, h6H, h6L, nullptr, nullptr);
    // 4. h7 = relu(h6 @ W7^T + b7) : M=4096, N=512, K=1024  (BM=64, 256 CTAs)
    gemm_mma<64, 1><<<dim3(4, 64), 256, SMEM64>>>(h6H, h6L, W7H, W7L, b7, 1024, 512,
                                                  h7, h7H, h7L, nullptr, nullptr);
    // 5. heads + fused class softmax: writes clsO/detO/cprob directly (BM=64, 64 CTAs)
    gemm_mma<64, 2><<<dim3(1, 64), 256, SMEM64>>>(h7H, h7L, WhdH, WhdL, bhd, 512, 0,
                                                  clsO, nullptr, nullptr, detO, cprob);

    // 6. fused det softmax + joint + video
    detjoint_kernel<<<B_ * K_, 256>>>(detO, cprob, joint, video);
}